// round 1
// baseline (speedup 1.0000x reference)
#include <cuda_runtime.h>

// Problem constants
#define BB 4
#define TT 2048
#define DD 1024
#define KK 64
#define RR (BB*TT)        // 8192 rows
#define NQ 192            // Q|K|V packed cols
#define CH 128            // chunk length
#define NC (TT/CH)        // 16 chunks per batch

// Scratch (device globals — no allocation allowed)
__device__ float g_Wpart[8 * DD * 128];          // split-K partials for W_pre@[Qf|Kf]
__device__ float g_Wqkv[DD * NQ];                // fused weights [D, 192]
__device__ float g_bqkv[NQ];
__device__ float g_QKV[RR * NQ];                 // [row, 192]
__device__ float g_S[BB * NC * KK * KK];         // per-chunk state sums
__device__ float g_H[BB * NC * KK * KK];         // exclusive prefix states
__device__ float g_Y[RR * KK];                   // attention output

// ---------------------------------------------------------------------------
// Kernel A: partial W_pre[D,T] @ [Q_filt | K_filt]  (split-K over T, 8 splits)
// tile 64 x 128, micro 4x8, grid (16, 8)
// ---------------------------------------------------------------------------
__global__ __launch_bounds__(256) void wfilt_partial(
    const float* __restrict__ W_pre,
    const float* __restrict__ Q_filt,
    const float* __restrict__ K_filt)
{
    __shared__ float Wp[64][33];
    __shared__ float Fs[32][128];
    int d0 = blockIdx.x * 64;
    int split = blockIdx.y;
    int tid = threadIdx.x;
    int ty = tid >> 4, tx = tid & 15;   // rows ty*4, cols tx*8
    float acc[4][8];
#pragma unroll
    for (int i = 0; i < 4; i++)
#pragma unroll
        for (int j = 0; j < 8; j++) acc[i][j] = 0.f;

    int t0 = split * 256;
    for (int kt = t0; kt < t0 + 256; kt += 32) {
        for (int i = tid; i < 64 * 32; i += 256) {
            int r = i >> 5, c = i & 31;
            Wp[r][c] = W_pre[(d0 + r) * TT + kt + c];
        }
        for (int i = tid; i < 32 * 128; i += 256) {
            int r = i >> 7, c = i & 127;
            Fs[r][c] = (c < 64) ? Q_filt[(kt + r) * KK + c]
                                : K_filt[(kt + r) * KK + (c - 64)];
        }
        __syncthreads();
#pragma unroll
        for (int kk = 0; kk < 32; kk++) {
            float a[4];
#pragma unroll
            for (int i = 0; i < 4; i++) a[i] = Wp[ty * 4 + i][kk];
            const float4* F4 = (const float4*)&Fs[kk][0];
            float4 b0 = F4[tx * 2 + 0];
            float4 b1 = F4[tx * 2 + 1];
            float bb[8] = {b0.x, b0.y, b0.z, b0.w, b1.x, b1.y, b1.z, b1.w};
#pragma unroll
            for (int i = 0; i < 4; i++)
#pragma unroll
                for (int j = 0; j < 8; j++) acc[i][j] += a[i] * bb[j];
        }
        __syncthreads();
    }
#pragma unroll
    for (int i = 0; i < 4; i++)
#pragma unroll
        for (int j = 0; j < 8; j++)
            g_Wpart[(split * DD + d0 + ty * 4 + i) * 128 + tx * 8 + j] = acc[i][j];
}

// ---------------------------------------------------------------------------
// Kernel A2: reduce split-K partials + copy W_v into fused weight matrix
// ---------------------------------------------------------------------------
__global__ void wqkv_finalize(const float* __restrict__ W_v)
{
    int idx = blockIdx.x * blockDim.x + threadIdx.x;
    if (idx >= DD * NQ) return;
    int d = idx / NQ, j = idx % NQ;
    if (j < 128) {
        float s = 0.f;
#pragma unroll
        for (int p = 0; p < 8; p++) s += g_Wpart[(p * DD + d) * 128 + j];
        g_Wqkv[idx] = s;
    } else {
        g_Wqkv[idx] = W_v[d * KK + (j - 128)];
    }
}

// ---------------------------------------------------------------------------
// Kernel A3: biases  bq = b_pre@Q_filt, bk = b_pre@K_filt, bv = b_v
// ---------------------------------------------------------------------------
__global__ void bias_kernel(const float* __restrict__ b_pre,
                            const float* __restrict__ Q_filt,
                            const float* __restrict__ K_filt,
                            const float* __restrict__ b_v)
{
    int j = threadIdx.x;
    if (j >= NQ) return;
    if (j < 128) {
        const float* F = (j < 64) ? Q_filt : K_filt;
        int col = j & 63;
        float s = 0.f;
        for (int t = 0; t < TT; t++) s += b_pre[t] * F[t * KK + col];
        g_bqkv[j] = s;
    } else {
        g_bqkv[j] = b_v[j - 128];
    }
}

// ---------------------------------------------------------------------------
// Kernel B: QKV = x[8192,1024] @ Wqkv[1024,192] + bqkv
// tile 128 x 64, micro 8x4, grid (64, 3)
// ---------------------------------------------------------------------------
__global__ __launch_bounds__(256) void qkv_gemm(const float* __restrict__ x)
{
    __shared__ float Xs[128][33];
    __shared__ float Ws[32][64];
    int r0 = blockIdx.x * 128;
    int n0 = blockIdx.y * 64;
    int tid = threadIdx.x;
    int ty = tid >> 4, tx = tid & 15;   // rows ty*8, cols tx*4
    float acc[8][4];
#pragma unroll
    for (int i = 0; i < 8; i++)
#pragma unroll
        for (int j = 0; j < 4; j++) acc[i][j] = 0.f;

    for (int kt = 0; kt < DD; kt += 32) {
        for (int i = tid; i < 128 * 32; i += 256) {
            int r = i >> 5, c = i & 31;
            Xs[r][c] = x[(r0 + r) * DD + kt + c];
        }
        for (int i = tid; i < 32 * 64; i += 256) {
            int r = i >> 6, c = i & 63;
            Ws[r][c] = g_Wqkv[(kt + r) * NQ + n0 + c];
        }
        __syncthreads();
#pragma unroll
        for (int kk = 0; kk < 32; kk++) {
            float a[8];
#pragma unroll
            for (int i = 0; i < 8; i++) a[i] = Xs[ty * 8 + i][kk];
            float4 bv = ((const float4*)&Ws[kk][0])[tx];
            float bb[4] = {bv.x, bv.y, bv.z, bv.w};
#pragma unroll
            for (int i = 0; i < 8; i++)
#pragma unroll
                for (int j = 0; j < 4; j++) acc[i][j] += a[i] * bb[j];
        }
        __syncthreads();
    }
    float4 bias = *(const float4*)&g_bqkv[n0 + tx * 4];
#pragma unroll
    for (int i = 0; i < 8; i++) {
        int row = r0 + ty * 8 + i;
        float4 o;
        o.x = acc[i][0] + bias.x;
        o.y = acc[i][1] + bias.y;
        o.z = acc[i][2] + bias.z;
        o.w = acc[i][3] + bias.w;
        *(float4*)&g_QKV[row * NQ + n0 + tx * 4] = o;
    }
}

// ---------------------------------------------------------------------------
// Kernel C1: per-chunk state sums  S_c[p,n] = sum_s decay_s * V[s,p]*Kf[s,n]
// grid 64 (b*16+c), 256 threads, micro 4x4
// ---------------------------------------------------------------------------
__global__ __launch_bounds__(256) void chunk_sum(const float* __restrict__ decay)
{
    __shared__ float Vs[64][65];
    __shared__ float Ks[64][65];
    int b = blockIdx.x >> 4, c = blockIdx.x & 15;
    int base = b * TT + c * CH;
    int tid = threadIdx.x;
    int ty = tid >> 4, tx = tid & 15;
    float acc[4][4];
#pragma unroll
    for (int i = 0; i < 4; i++)
#pragma unroll
        for (int j = 0; j < 4; j++) acc[i][j] = 0.f;

    for (int st = 0; st < CH; st += 64) {
        for (int i = tid; i < 64 * 64; i += 256) {
            int r = i >> 6, k = i & 63;
            int row = base + st + r;
            float d = decay[c * CH + st + r];
            Vs[r][k] = g_QKV[row * NQ + 128 + k];
            Ks[r][k] = g_QKV[row * NQ + 64 + k] * d;
        }
        __syncthreads();
#pragma unroll 8
        for (int s = 0; s < 64; s++) {
            float a[4], bb[4];
#pragma unroll
            for (int i = 0; i < 4; i++) a[i] = Vs[s][ty * 4 + i];
#pragma unroll
            for (int j = 0; j < 4; j++) bb[j] = Ks[s][tx * 4 + j];
#pragma unroll
            for (int i = 0; i < 4; i++)
#pragma unroll
                for (int j = 0; j < 4; j++) acc[i][j] += a[i] * bb[j];
        }
        __syncthreads();
    }
    int sb = (b * NC + c) * KK * KK;
#pragma unroll
    for (int i = 0; i < 4; i++)
#pragma unroll
        for (int j = 0; j < 4; j++)
            g_S[sb + (ty * 4 + i) * KK + tx * 4 + j] = acc[i][j];
}

// ---------------------------------------------------------------------------
// Kernel C2: exclusive prefix over chunks (per batch, per matrix element)
// grid 16 (b*4 + quarter), 1024 threads
// ---------------------------------------------------------------------------
__global__ void chunk_prefix()
{
    int b = blockIdx.x >> 2;
    int e = (blockIdx.x & 3) * 1024 + threadIdx.x;   // 0..4095
    float acc = 0.f;
    for (int c = 0; c < NC; c++) {
        int idx = (b * NC + c) * KK * KK + e;
        g_H[idx] = acc;
        acc += g_S[idx];
    }
}

// ---------------------------------------------------------------------------
// Kernel C3: Y_chunk = Q @ H_prev  +  causal intra-chunk (Q.V) decay Kf
// grid 64, 256 threads: thread = (row t in 0..127, half of 64 n-cols)
// smem: Qt[k][t] 32KB + union{Hs[64*64] | Vs[32*64]+Kfs[32*64]} 16KB = 48KB
// ---------------------------------------------------------------------------
__global__ __launch_bounds__(256) void attn_kernel(const float* __restrict__ decay)
{
    __shared__ float Qt[KK][CH];       // transposed Q: [k][t]
    __shared__ float Reg[4096];        // union buffer
    int b = blockIdx.x >> 4, c = blockIdx.x & 15;
    int base = b * TT + c * CH;
    int tid = threadIdx.x;
    int row = tid >> 1;                // local t
    int half = tid & 1;                // n block: half*32

    // load Q transposed (uncoalesced global, conflict-free smem)
    for (int i = tid; i < KK * CH; i += 256) {
        int r = i & (CH - 1), k = i >> 7;
        Qt[k][r] = g_QKV[(base + r) * NQ + k];
    }
    // load H_prev
    int hb = (b * NC + c) * KK * KK;
    for (int i = tid; i < KK * KK; i += 256) Reg[i] = g_H[hb + i];
    __syncthreads();

    // Q row into registers
    float q[KK];
#pragma unroll
    for (int k = 0; k < KK; k++) q[k] = Qt[k][row];

    float y[32];
#pragma unroll
    for (int j = 0; j < 32; j++) y[j] = 0.f;

    // inter-chunk: y[n] += sum_k q[k] * H[k][n]
    {
        const float4* H4 = (const float4*)Reg;
#pragma unroll
        for (int k = 0; k < KK; k++) {
            float qk = q[k];
#pragma unroll
            for (int jj = 0; jj < 8; jj++) {
                float4 h = H4[k * 16 + half * 8 + jj];
                y[jj * 4 + 0] += qk * h.x;
                y[jj * 4 + 1] += qk * h.y;
                y[jj * 4 + 2] += qk * h.z;
                y[jj * 4 + 3] += qk * h.w;
            }
        }
    }
    __syncthreads();

    // intra-chunk causal, s-tiles of 32
    for (int st = 0; st < CH; st += 32) {
        for (int i = tid; i < 2048; i += 256) {
            int s = i >> 6, k = i & 63;
            int grow = (base + st + s) * NQ;
            Reg[i]        = g_QKV[grow + 128 + k];                      // V
            Reg[2048 + i] = g_QKV[grow + 64 + k] * decay[c * CH + st + s]; // Kf*d
        }
        __syncthreads();
        if (row >= st) {
            int sm = row - st + 1;
            if (sm > 32) sm = 32;
            const float4* V4 = (const float4*)Reg;
            const float4* F4 = (const float4*)(Reg + 2048);
            for (int s = 0; s < sm; s++) {
                float sc = 0.f;
#pragma unroll
                for (int kk = 0; kk < 16; kk++) {
                    float4 v = V4[s * 16 + kk];
                    sc += q[kk * 4 + 0] * v.x + q[kk * 4 + 1] * v.y
                        + q[kk * 4 + 2] * v.z + q[kk * 4 + 3] * v.w;
                }
#pragma unroll
                for (int jj = 0; jj < 8; jj++) {
                    float4 f = F4[s * 16 + half * 8 + jj];
                    y[jj * 4 + 0] += sc * f.x;
                    y[jj * 4 + 1] += sc * f.y;
                    y[jj * 4 + 2] += sc * f.z;
                    y[jj * 4 + 3] += sc * f.w;
                }
            }
        }
        __syncthreads();
    }

    float* yout = &g_Y[(base + row) * KK + half * 32];
#pragma unroll
    for (int jj = 0; jj < 8; jj++) {
        float4 o = {y[jj * 4 + 0], y[jj * 4 + 1], y[jj * 4 + 2], y[jj * 4 + 3]};
        *(float4*)&yout[jj * 4] = o;
    }
}

// ---------------------------------------------------------------------------
// Kernel D: out = Y[8192,64] @ W_o[64,1024] + b_o
// tile 64 x 128, micro 4x8, grid (128, 8)
// ---------------------------------------------------------------------------
__global__ __launch_bounds__(256) void out_gemm(const float* __restrict__ W_o,
                                                const float* __restrict__ b_o,
                                                float* __restrict__ out)
{
    __shared__ float Yt[32][65];       // [k][row]
    __shared__ float Wos[32][128];
    int r0 = blockIdx.x * 64;
    int n0 = blockIdx.y * 128;
    int tid = threadIdx.x;
    int ty = tid >> 4, tx = tid & 15;  // rows ty*4, cols tx*8
    float acc[4][8];
#pragma unroll
    for (int i = 0; i < 4; i++)
#pragma unroll
        for (int j = 0; j < 8; j++) acc[i][j] = 0.f;

    for (int kt = 0; kt < KK; kt += 32) {
        for (int i = tid; i < 64 * 32; i += 256) {
            int r = i >> 5, c = i & 31;
            Yt[c][r] = g_Y[(r0 + r) * KK + kt + c];
        }
        for (int i = tid; i < 32 * 128; i += 256) {
            int r = i >> 7, c = i & 127;
            Wos[r][c] = W_o[(kt + r) * DD + n0 + c];
        }
        __syncthreads();
#pragma unroll
        for (int kk = 0; kk < 32; kk++) {
            float a[4];
#pragma unroll
            for (int i = 0; i < 4; i++) a[i] = Yt[kk][ty * 4 + i];
            const float4* W4 = (const float4*)&Wos[kk][0];
            float4 b0 = W4[tx * 2 + 0];
            float4 b1 = W4[tx * 2 + 1];
            float bb[8] = {b0.x, b0.y, b0.z, b0.w, b1.x, b1.y, b1.z, b1.w};
#pragma unroll
            for (int i = 0; i < 4; i++)
#pragma unroll
                for (int j = 0; j < 8; j++) acc[i][j] += a[i] * bb[j];
        }
        __syncthreads();
    }
    float4 bl = *(const float4*)&b_o[n0 + tx * 8];
    float4 bh = *(const float4*)&b_o[n0 + tx * 8 + 4];
    float bias[8] = {bl.x, bl.y, bl.z, bl.w, bh.x, bh.y, bh.z, bh.w};
#pragma unroll
    for (int i = 0; i < 4; i++) {
        int row = r0 + ty * 4 + i;
        float4 o0 = {acc[i][0] + bias[0], acc[i][1] + bias[1],
                     acc[i][2] + bias[2], acc[i][3] + bias[3]};
        float4 o1 = {acc[i][4] + bias[4], acc[i][5] + bias[5],
                     acc[i][6] + bias[6], acc[i][7] + bias[7]};
        *(float4*)&out[row * DD + n0 + tx * 8]     = o0;
        *(float4*)&out[row * DD + n0 + tx * 8 + 4] = o1;
    }
}

// ---------------------------------------------------------------------------
extern "C" void kernel_launch(void* const* d_in, const int* in_sizes, int n_in,
                              void* d_out, int out_size)
{
    const float* x      = (const float*)d_in[0];
    const float* W_pre  = (const float*)d_in[1];
    const float* b_pre  = (const float*)d_in[2];
    const float* Q_filt = (const float*)d_in[3];
    const float* K_filt = (const float*)d_in[4];
    const float* W_v    = (const float*)d_in[5];
    const float* b_v    = (const float*)d_in[6];
    const float* W_o    = (const float*)d_in[7];
    const float* b_o    = (const float*)d_in[8];
    const float* decay  = (const float*)d_in[9];
    float* out = (float*)d_out;

    wfilt_partial<<<dim3(16, 8), 256>>>(W_pre, Q_filt, K_filt);
    wqkv_finalize<<<(DD * NQ + 255) / 256, 256>>>(W_v);
    bias_kernel<<<1, 192>>>(b_pre, Q_filt, K_filt, b_v);
    qkv_gemm<<<dim3(64, 3), 256>>>(x);
    chunk_sum<<<64, 256>>>(decay);
    chunk_prefix<<<16, 1024>>>();
    attn_kernel<<<64, 256>>>(decay);
    out_gemm<<<dim3(128, 8), 256>>>(W_o, b_o, out);
}

// round 2
// speedup vs baseline: 1.2246x; 1.2246x over previous
#include <cuda_runtime.h>
#include <cuda_bf16.h>
#include <cstdint>

// Problem constants
#define BB 4
#define TT 2048
#define DD 1024
#define KK 64
#define RR (BB*TT)        // 8192 rows
#define NQ 192            // Q|K|V packed cols
#define CH 128            // chunk length
#define NC (TT/CH)        // 16 chunks per batch

// Scratch (device globals — no allocation allowed)
__device__ float g_Wpart[8 * DD * 128];          // split-K partials for W_pre@[Qf|Kf]
__device__ float g_Wqkv[DD * NQ];                // fused weights [D, 192]
__device__ float g_bqkv[NQ];
__device__ float g_QKV[RR * NQ];                 // [row, 192]
__device__ float g_S[BB * NC * KK * KK];         // per-chunk state sums
__device__ float g_H[BB * NC * KK * KK];         // exclusive prefix states
__device__ float g_Y[RR * KK];                   // attention output
// bf16 split operands for tensor-core QKV GEMM
__device__ __nv_bfloat16 g_xhi[RR * DD];
__device__ __nv_bfloat16 g_xlo[RR * DD];
__device__ __nv_bfloat16 g_Whi[DD * NQ];
__device__ __nv_bfloat16 g_Wlo[DD * NQ];

// ---------------------------------------------------------------------------
// mma.sync helpers
// ---------------------------------------------------------------------------
__device__ __forceinline__ uint32_t smaddr(const void* p) {
    return (uint32_t)__cvta_generic_to_shared(p);
}
__device__ __forceinline__ void ldsm_x4(uint32_t& r0, uint32_t& r1,
                                        uint32_t& r2, uint32_t& r3, uint32_t a) {
    asm volatile("ldmatrix.sync.aligned.m8n8.x4.shared.b16 {%0,%1,%2,%3}, [%4];"
                 : "=r"(r0), "=r"(r1), "=r"(r2), "=r"(r3) : "r"(a));
}
__device__ __forceinline__ void ldsm_x4_t(uint32_t& r0, uint32_t& r1,
                                          uint32_t& r2, uint32_t& r3, uint32_t a) {
    asm volatile("ldmatrix.sync.aligned.m8n8.x4.trans.shared.b16 {%0,%1,%2,%3}, [%4];"
                 : "=r"(r0), "=r"(r1), "=r"(r2), "=r"(r3) : "r"(a));
}
__device__ __forceinline__ void mma_bf16(float* c, const uint32_t* a,
                                         uint32_t b0, uint32_t b1) {
    asm volatile(
        "mma.sync.aligned.m16n8k16.row.col.f32.bf16.bf16.f32 "
        "{%0,%1,%2,%3}, {%4,%5,%6,%7}, {%8,%9}, {%0,%1,%2,%3};"
        : "+f"(c[0]), "+f"(c[1]), "+f"(c[2]), "+f"(c[3])
        : "r"(a[0]), "r"(a[1]), "r"(a[2]), "r"(a[3]), "r"(b0), "r"(b1));
}

// ---------------------------------------------------------------------------
// Kernel A: partial W_pre[D,T] @ [Q_filt | K_filt]  (split-K over T, 8 splits)
// ---------------------------------------------------------------------------
__global__ __launch_bounds__(256) void wfilt_partial(
    const float* __restrict__ W_pre,
    const float* __restrict__ Q_filt,
    const float* __restrict__ K_filt)
{
    __shared__ float Wp[64][33];
    __shared__ float Fs[32][128];
    int d0 = blockIdx.x * 64;
    int split = blockIdx.y;
    int tid = threadIdx.x;
    int ty = tid >> 4, tx = tid & 15;
    float acc[4][8];
#pragma unroll
    for (int i = 0; i < 4; i++)
#pragma unroll
        for (int j = 0; j < 8; j++) acc[i][j] = 0.f;

    int t0 = split * 256;
    for (int kt = t0; kt < t0 + 256; kt += 32) {
        for (int i = tid; i < 64 * 32; i += 256) {
            int r = i >> 5, c = i & 31;
            Wp[r][c] = W_pre[(d0 + r) * TT + kt + c];
        }
        for (int i = tid; i < 32 * 128; i += 256) {
            int r = i >> 7, c = i & 127;
            Fs[r][c] = (c < 64) ? Q_filt[(kt + r) * KK + c]
                                : K_filt[(kt + r) * KK + (c - 64)];
        }
        __syncthreads();
#pragma unroll
        for (int kk = 0; kk < 32; kk++) {
            float a[4];
#pragma unroll
            for (int i = 0; i < 4; i++) a[i] = Wp[ty * 4 + i][kk];
            const float4* F4 = (const float4*)&Fs[kk][0];
            float4 b0 = F4[tx * 2 + 0];
            float4 b1 = F4[tx * 2 + 1];
            float bb[8] = {b0.x, b0.y, b0.z, b0.w, b1.x, b1.y, b1.z, b1.w};
#pragma unroll
            for (int i = 0; i < 4; i++)
#pragma unroll
                for (int j = 0; j < 8; j++) acc[i][j] += a[i] * bb[j];
        }
        __syncthreads();
    }
#pragma unroll
    for (int i = 0; i < 4; i++)
#pragma unroll
        for (int j = 0; j < 8; j++)
            g_Wpart[(split * DD + d0 + ty * 4 + i) * 128 + tx * 8 + j] = acc[i][j];
}

// ---------------------------------------------------------------------------
// Kernel A2: reduce split-K partials + copy W_v into fused weight matrix
// ---------------------------------------------------------------------------
__global__ void wqkv_finalize(const float* __restrict__ W_v)
{
    int idx = blockIdx.x * blockDim.x + threadIdx.x;
    if (idx >= DD * NQ) return;
    int d = idx / NQ, j = idx % NQ;
    if (j < 128) {
        float s = 0.f;
#pragma unroll
        for (int p = 0; p < 8; p++) s += g_Wpart[(p * DD + d) * 128 + j];
        g_Wqkv[idx] = s;
    } else {
        g_Wqkv[idx] = W_v[d * KK + (j - 128)];
    }
}

// ---------------------------------------------------------------------------
// Kernel A3: biases
// ---------------------------------------------------------------------------
__global__ void bias_kernel(const float* __restrict__ b_pre,
                            const float* __restrict__ Q_filt,
                            const float* __restrict__ K_filt,
                            const float* __restrict__ b_v)
{
    int j = threadIdx.x;
    if (j >= NQ) return;
    if (j < 128) {
        const float* F = (j < 64) ? Q_filt : K_filt;
        int col = j & 63;
        float s = 0.f;
        for (int t = 0; t < TT; t++) s += b_pre[t] * F[t * KK + col];
        g_bqkv[j] = s;
    } else {
        g_bqkv[j] = b_v[j - 128];
    }
}

// ---------------------------------------------------------------------------
// Split kernels: fp32 -> bf16 hi/lo pairs
// ---------------------------------------------------------------------------
__global__ __launch_bounds__(256) void split_x(const float* __restrict__ x)
{
    int i = blockIdx.x * blockDim.x + threadIdx.x;   // one float4 per thread
    float4 v = ((const float4*)x)[i];
    __nv_bfloat16 h[4], l[4];
    float f[4] = {v.x, v.y, v.z, v.w};
#pragma unroll
    for (int j = 0; j < 4; j++) {
        h[j] = __float2bfloat16_rn(f[j]);
        l[j] = __float2bfloat16_rn(f[j] - __bfloat162float(h[j]));
    }
    *(uint2*)&g_xhi[i * 4] = *(uint2*)h;
    *(uint2*)&g_xlo[i * 4] = *(uint2*)l;
}

__global__ __launch_bounds__(256) void split_w()
{
    int i = blockIdx.x * blockDim.x + threadIdx.x;   // one float4 per thread
    float4 v = ((const float4*)g_Wqkv)[i];
    __nv_bfloat16 h[4], l[4];
    float f[4] = {v.x, v.y, v.z, v.w};
#pragma unroll
    for (int j = 0; j < 4; j++) {
        h[j] = __float2bfloat16_rn(f[j]);
        l[j] = __float2bfloat16_rn(f[j] - __bfloat162float(h[j]));
    }
    *(uint2*)&g_Whi[i * 4] = *(uint2*)h;
    *(uint2*)&g_Wlo[i * 4] = *(uint2*)l;
}

// ---------------------------------------------------------------------------
// Kernel B: QKV GEMM on tensor cores, bf16 split (3 phases packed as K=3072)
// phase 0: A_hi*B_hi ; phase 1: A_lo*B_hi ; phase 2: A_hi*B_lo
// Block tile 128x64, 8 warps (4m x 2n), warp tile 32x32, k-step 32.
// ---------------------------------------------------------------------------
#define APITCH 40
#define BPITCH 72
__global__ __launch_bounds__(256) void qkv_mma()
{
    __shared__ __nv_bfloat16 As[128][APITCH];
    __shared__ __nv_bfloat16 Bs[32][BPITCH];
    int r0 = blockIdx.x * 128;
    int n0 = blockIdx.y * 64;
    int tid = threadIdx.x;
    int lane = tid & 31, w = tid >> 5;
    int wm = (w & 3) * 32, wn = (w >> 2) * 32;

    float acc[2][4][4];
#pragma unroll
    for (int mt = 0; mt < 2; mt++)
#pragma unroll
        for (int nt = 0; nt < 4; nt++)
#pragma unroll
            for (int r = 0; r < 4; r++) acc[mt][nt][r] = 0.f;

    // per-thread global load coords
    int ar = tid >> 2, ac = (tid & 3) * 8;      // A: rows ar, ar+64 ; 8 bf16 each
    int br = tid >> 3, bc = (tid & 7) * 8;      // B: one 8-bf16 vector

    float4 a0v, a1v, bv;
    // prefetch tile 0
    {
        const __nv_bfloat16* Asrc = g_xhi;
        const __nv_bfloat16* Bsrc = g_Whi;
        a0v = *(const float4*)&Asrc[(r0 + ar) * DD + ac];
        a1v = *(const float4*)&Asrc[(r0 + ar + 64) * DD + ac];
        bv  = *(const float4*)&Bsrc[br * NQ + n0 + bc];
    }

    for (int it = 0; it < 96; it++) {
        // commit prefetched tile to smem
        *(float4*)&As[ar][ac]      = a0v;
        *(float4*)&As[ar + 64][ac] = a1v;
        *(float4*)&Bs[br][bc]      = bv;
        __syncthreads();

        // prefetch next tile
        if (it + 1 < 96) {
            int kt = (it + 1) * 32;
            int phase = kt >> 10;
            int kk = kt & 1023;
            const __nv_bfloat16* Asrc = (phase == 1) ? g_xlo : g_xhi;
            const __nv_bfloat16* Bsrc = (phase == 2) ? g_Wlo : g_Whi;
            a0v = *(const float4*)&Asrc[(r0 + ar) * DD + kk + ac];
            a1v = *(const float4*)&Asrc[(r0 + ar + 64) * DD + kk + ac];
            bv  = *(const float4*)&Bsrc[(kk + br) * NQ + n0 + bc];
        }

        // compute 2 k16 steps
#pragma unroll
        for (int ks = 0; ks < 2; ks++) {
            int k = ks * 16;
            uint32_t a[2][4];
#pragma unroll
            for (int mt = 0; mt < 2; mt++) {
                uint32_t ad = smaddr(&As[wm + mt * 16 + (lane & 15)][k + ((lane >> 4) << 3)]);
                ldsm_x4(a[mt][0], a[mt][1], a[mt][2], a[mt][3], ad);
            }
            uint32_t b[2][4];
#pragma unroll
            for (int nb = 0; nb < 2; nb++) {
                uint32_t bd = smaddr(&Bs[k + (lane & 15)][wn + nb * 16 + ((lane >> 4) << 3)]);
                ldsm_x4_t(b[nb][0], b[nb][1], b[nb][2], b[nb][3], bd);
            }
#pragma unroll
            for (int mt = 0; mt < 2; mt++)
#pragma unroll
                for (int nt = 0; nt < 4; nt++) {
                    int nb = nt >> 1, pr = nt & 1;
                    mma_bf16(acc[mt][nt], a[mt], b[nb][pr * 2], b[nb][pr * 2 + 1]);
                }
        }
        __syncthreads();
    }

    // epilogue: add bias, write fp32 QKV
    int gr = lane >> 2, tc = (lane & 3) * 2;
#pragma unroll
    for (int mt = 0; mt < 2; mt++)
#pragma unroll
        for (int nt = 0; nt < 4; nt++) {
            int row = r0 + wm + mt * 16 + gr;
            int col = n0 + wn + nt * 8 + tc;
            float bb0 = g_bqkv[col], bb1 = g_bqkv[col + 1];
            g_QKV[row * NQ + col]           = acc[mt][nt][0] + bb0;
            g_QKV[row * NQ + col + 1]       = acc[mt][nt][1] + bb1;
            g_QKV[(row + 8) * NQ + col]     = acc[mt][nt][2] + bb0;
            g_QKV[(row + 8) * NQ + col + 1] = acc[mt][nt][3] + bb1;
        }
}

// ---------------------------------------------------------------------------
// Kernel C1: per-chunk state sums  S_c[p,n] = sum_s decay_s * V[s,p]*Kf[s,n]
// ---------------------------------------------------------------------------
__global__ __launch_bounds__(256) void chunk_sum(const float* __restrict__ decay)
{
    __shared__ float Vs[64][65];
    __shared__ float Ks[64][65];
    int b = blockIdx.x >> 4, c = blockIdx.x & 15;
    int base = b * TT + c * CH;
    int tid = threadIdx.x;
    int ty = tid >> 4, tx = tid & 15;
    float acc[4][4];
#pragma unroll
    for (int i = 0; i < 4; i++)
#pragma unroll
        for (int j = 0; j < 4; j++) acc[i][j] = 0.f;

    for (int st = 0; st < CH; st += 64) {
        for (int i = tid; i < 64 * 64; i += 256) {
            int r = i >> 6, k = i & 63;
            int row = base + st + r;
            float d = decay[c * CH + st + r];
            Vs[r][k] = g_QKV[row * NQ + 128 + k];
            Ks[r][k] = g_QKV[row * NQ + 64 + k] * d;
        }
        __syncthreads();
#pragma unroll 8
        for (int s = 0; s < 64; s++) {
            float a[4], bb[4];
#pragma unroll
            for (int i = 0; i < 4; i++) a[i] = Vs[s][ty * 4 + i];
#pragma unroll
            for (int j = 0; j < 4; j++) bb[j] = Ks[s][tx * 4 + j];
#pragma unroll
            for (int i = 0; i < 4; i++)
#pragma unroll
                for (int j = 0; j < 4; j++) acc[i][j] += a[i] * bb[j];
        }
        __syncthreads();
    }
    int sb = (b * NC + c) * KK * KK;
#pragma unroll
    for (int i = 0; i < 4; i++)
#pragma unroll
        for (int j = 0; j < 4; j++)
            g_S[sb + (ty * 4 + i) * KK + tx * 4 + j] = acc[i][j];
}

// ---------------------------------------------------------------------------
// Kernel C2: exclusive prefix over chunks
// ---------------------------------------------------------------------------
__global__ void chunk_prefix()
{
    int b = blockIdx.x >> 2;
    int e = (blockIdx.x & 3) * 1024 + threadIdx.x;
    float acc = 0.f;
    for (int c = 0; c < NC; c++) {
        int idx = (b * NC + c) * KK * KK + e;
        g_H[idx] = acc;
        acc += g_S[idx];
    }
}

// ---------------------------------------------------------------------------
// Kernel C3: Y_chunk = Q @ H_prev  +  causal intra-chunk (Q.V) decay Kf
// ---------------------------------------------------------------------------
__global__ __launch_bounds__(256) void attn_kernel(const float* __restrict__ decay)
{
    __shared__ float Qt[KK][CH];
    __shared__ float Reg[4096];
    int b = blockIdx.x >> 4, c = blockIdx.x & 15;
    int base = b * TT + c * CH;
    int tid = threadIdx.x;
    int row = tid >> 1;
    int half = tid & 1;

    for (int i = tid; i < KK * CH; i += 256) {
        int r = i & (CH - 1), k = i >> 7;
        Qt[k][r] = g_QKV[(base + r) * NQ + k];
    }
    int hb = (b * NC + c) * KK * KK;
    for (int i = tid; i < KK * KK; i += 256) Reg[i] = g_H[hb + i];
    __syncthreads();

    float q[KK];
#pragma unroll
    for (int k = 0; k < KK; k++) q[k] = Qt[k][row];

    float y[32];
#pragma unroll
    for (int j = 0; j < 32; j++) y[j] = 0.f;

    {
        const float4* H4 = (const float4*)Reg;
#pragma unroll
        for (int k = 0; k < KK; k++) {
            float qk = q[k];
#pragma unroll
            for (int jj = 0; jj < 8; jj++) {
                float4 h = H4[k * 16 + half * 8 + jj];
                y[jj * 4 + 0] += qk * h.x;
                y[jj * 4 + 1] += qk * h.y;
                y[jj * 4 + 2] += qk * h.z;
                y[jj * 4 + 3] += qk * h.w;
            }
        }
    }
    __syncthreads();

    for (int st = 0; st < CH; st += 32) {
        for (int i = tid; i < 2048; i += 256) {
            int s = i >> 6, k = i & 63;
            int grow = (base + st + s) * NQ;
            Reg[i]        = g_QKV[grow + 128 + k];
            Reg[2048 + i] = g_QKV[grow + 64 + k] * decay[c * CH + st + s];
        }
        __syncthreads();
        if (row >= st) {
            int sm = row - st + 1;
            if (sm > 32) sm = 32;
            const float4* V4 = (const float4*)Reg;
            const float4* F4 = (const float4*)(Reg + 2048);
            for (int s = 0; s < sm; s++) {
                float sc = 0.f;
#pragma unroll
                for (int kk = 0; kk < 16; kk++) {
                    float4 v = V4[s * 16 + kk];
                    sc += q[kk * 4 + 0] * v.x + q[kk * 4 + 1] * v.y
                        + q[kk * 4 + 2] * v.z + q[kk * 4 + 3] * v.w;
                }
#pragma unroll
                for (int jj = 0; jj < 8; jj++) {
                    float4 f = F4[s * 16 + half * 8 + jj];
                    y[jj * 4 + 0] += sc * f.x;
                    y[jj * 4 + 1] += sc * f.y;
                    y[jj * 4 + 2] += sc * f.z;
                    y[jj * 4 + 3] += sc * f.w;
                }
            }
        }
        __syncthreads();
    }

    float* yout = &g_Y[(base + row) * KK + half * 32];
#pragma unroll
    for (int jj = 0; jj < 8; jj++) {
        float4 o = {y[jj * 4 + 0], y[jj * 4 + 1], y[jj * 4 + 2], y[jj * 4 + 3]};
        *(float4*)&yout[jj * 4] = o;
    }
}

// ---------------------------------------------------------------------------
// Kernel D: out = Y[8192,64] @ W_o[64,1024] + b_o
// ---------------------------------------------------------------------------
__global__ __launch_bounds__(256) void out_gemm(const float* __restrict__ W_o,
                                                const float* __restrict__ b_o,
                                                float* __restrict__ out)
{
    __shared__ float Yt[32][65];
    __shared__ float Wos[32][128];
    int r0 = blockIdx.x * 64;
    int n0 = blockIdx.y * 128;
    int tid = threadIdx.x;
    int ty = tid >> 4, tx = tid & 15;
    float acc[4][8];
#pragma unroll
    for (int i = 0; i < 4; i++)
#pragma unroll
        for (int j = 0; j < 8; j++) acc[i][j] = 0.f;

    for (int kt = 0; kt < KK; kt += 32) {
        for (int i = tid; i < 64 * 32; i += 256) {
            int r = i >> 5, c = i & 31;
            Yt[c][r] = g_Y[(r0 + r) * KK + kt + c];
        }
        for (int i = tid; i < 32 * 128; i += 256) {
            int r = i >> 7, c = i & 127;
            Wos[r][c] = W_o[(kt + r) * DD + n0 + c];
        }
        __syncthreads();
#pragma unroll
        for (int kk = 0; kk < 32; kk++) {
            float a[4];
#pragma unroll
            for (int i = 0; i < 4; i++) a[i] = Yt[kk][ty * 4 + i];
            const float4* W4 = (const float4*)&Wos[kk][0];
            float4 b0 = W4[tx * 2 + 0];
            float4 b1 = W4[tx * 2 + 1];
            float bb[8] = {b0.x, b0.y, b0.z, b0.w, b1.x, b1.y, b1.z, b1.w};
#pragma unroll
            for (int i = 0; i < 4; i++)
#pragma unroll
                for (int j = 0; j < 8; j++) acc[i][j] += a[i] * bb[j];
        }
        __syncthreads();
    }
    float4 bl = *(const float4*)&b_o[n0 + tx * 8];
    float4 bh = *(const float4*)&b_o[n0 + tx * 8 + 4];
    float bias[8] = {bl.x, bl.y, bl.z, bl.w, bh.x, bh.y, bh.z, bh.w};
#pragma unroll
    for (int i = 0; i < 4; i++) {
        int row = r0 + ty * 4 + i;
        float4 o0 = {acc[i][0] + bias[0], acc[i][1] + bias[1],
                     acc[i][2] + bias[2], acc[i][3] + bias[3]};
        float4 o1 = {acc[i][4] + bias[4], acc[i][5] + bias[5],
                     acc[i][6] + bias[6], acc[i][7] + bias[7]};
        *(float4*)&out[row * DD + n0 + tx * 8]     = o0;
        *(float4*)&out[row * DD + n0 + tx * 8 + 4] = o1;
    }
}

// ---------------------------------------------------------------------------
extern "C" void kernel_launch(void* const* d_in, const int* in_sizes, int n_in,
                              void* d_out, int out_size)
{
    const float* x      = (const float*)d_in[0];
    const float* W_pre  = (const float*)d_in[1];
    const float* b_pre  = (const float*)d_in[2];
    const float* Q_filt = (const float*)d_in[3];
    const float* K_filt = (const float*)d_in[4];
    const float* W_v    = (const float*)d_in[5];
    const float* b_v    = (const float*)d_in[6];
    const float* W_o    = (const float*)d_in[7];
    const float* b_o    = (const float*)d_in[8];
    const float* decay  = (const float*)d_in[9];
    float* out = (float*)d_out;

    split_x<<<(RR * DD / 4) / 256, 256>>>(x);
    wfilt_partial<<<dim3(16, 8), 256>>>(W_pre, Q_filt, K_filt);
    wqkv_finalize<<<(DD * NQ + 255) / 256, 256>>>(W_v);
    bias_kernel<<<1, 192>>>(b_pre, Q_filt, K_filt, b_v);
    split_w<<<(DD * NQ / 4) / 256, 256>>>();
    qkv_mma<<<dim3(64, 3), 256>>>();
    chunk_sum<<<64, 256>>>(decay);
    chunk_prefix<<<16, 1024>>>();
    attn_kernel<<<64, 256>>>(decay);
    out_gemm<<<dim3(128, 8), 256>>>(W_o, b_o, out);
}

// round 3
// speedup vs baseline: 1.5364x; 1.2546x over previous
#include <cuda_runtime.h>
#include <cuda_bf16.h>
#include <cstdint>

// Problem constants
#define BB 4
#define TT 2048
#define DD 1024
#define KK 64
#define RR (BB*TT)        // 8192 rows
#define NQ 192            // Q|K|V packed cols
#define CH 128            // chunk length
#define NC (TT/CH)        // 16 chunks per batch

// Scratch (device globals — no allocation allowed)
__device__ float g_Wpart[8 * DD * 128];          // split-K partials for W_pre@[Qf|Kf]
__device__ float g_Wqkv[DD * NQ];                // fused weights [D, 192]
__device__ float g_bqkv[NQ];
__device__ float g_QKV[RR * NQ];                 // [row, 192]
__device__ float g_S[BB * NC * KK * KK];         // per-chunk state sums
__device__ float g_H[BB * NC * KK * KK];         // exclusive prefix states
__device__ float g_Y[RR * KK];                   // attention output
// bf16 split operands for tensor-core QKV GEMM
__device__ __nv_bfloat16 g_xhi[RR * DD];
__device__ __nv_bfloat16 g_xlo[RR * DD];
__device__ __nv_bfloat16 g_Whi[DD * NQ];
__device__ __nv_bfloat16 g_Wlo[DD * NQ];

// ---------------------------------------------------------------------------
// mma.sync helpers
// ---------------------------------------------------------------------------
__device__ __forceinline__ uint32_t smaddr(const void* p) {
    return (uint32_t)__cvta_generic_to_shared(p);
}
__device__ __forceinline__ void ldsm_x4(uint32_t& r0, uint32_t& r1,
                                        uint32_t& r2, uint32_t& r3, uint32_t a) {
    asm volatile("ldmatrix.sync.aligned.m8n8.x4.shared.b16 {%0,%1,%2,%3}, [%4];"
                 : "=r"(r0), "=r"(r1), "=r"(r2), "=r"(r3) : "r"(a));
}
__device__ __forceinline__ void ldsm_x4_t(uint32_t& r0, uint32_t& r1,
                                          uint32_t& r2, uint32_t& r3, uint32_t a) {
    asm volatile("ldmatrix.sync.aligned.m8n8.x4.trans.shared.b16 {%0,%1,%2,%3}, [%4];"
                 : "=r"(r0), "=r"(r1), "=r"(r2), "=r"(r3) : "r"(a));
}
__device__ __forceinline__ void mma_bf16(float* c, const uint32_t* a,
                                         uint32_t b0, uint32_t b1) {
    asm volatile(
        "mma.sync.aligned.m16n8k16.row.col.f32.bf16.bf16.f32 "
        "{%0,%1,%2,%3}, {%4,%5,%6,%7}, {%8,%9}, {%0,%1,%2,%3};"
        : "+f"(c[0]), "+f"(c[1]), "+f"(c[2]), "+f"(c[3])
        : "r"(a[0]), "r"(a[1]), "r"(a[2]), "r"(a[3]), "r"(b0), "r"(b1));
}

// ---------------------------------------------------------------------------
// Kernel A: partial W_pre[D,T] @ [Q_filt | K_filt]  (split-K over T, 8 splits)
// ---------------------------------------------------------------------------
__global__ __launch_bounds__(256) void wfilt_partial(
    const float* __restrict__ W_pre,
    const float* __restrict__ Q_filt,
    const float* __restrict__ K_filt)
{
    __shared__ float Wp[64][33];
    __shared__ float Fs[32][128];
    int d0 = blockIdx.x * 64;
    int split = blockIdx.y;
    int tid = threadIdx.x;
    int ty = tid >> 4, tx = tid & 15;
    float acc[4][8];
#pragma unroll
    for (int i = 0; i < 4; i++)
#pragma unroll
        for (int j = 0; j < 8; j++) acc[i][j] = 0.f;

    int t0 = split * 256;
    for (int kt = t0; kt < t0 + 256; kt += 32) {
        for (int i = tid; i < 64 * 32; i += 256) {
            int r = i >> 5, c = i & 31;
            Wp[r][c] = W_pre[(d0 + r) * TT + kt + c];
        }
        for (int i = tid; i < 32 * 128; i += 256) {
            int r = i >> 7, c = i & 127;
            Fs[r][c] = (c < 64) ? Q_filt[(kt + r) * KK + c]
                                : K_filt[(kt + r) * KK + (c - 64)];
        }
        __syncthreads();
#pragma unroll
        for (int kk = 0; kk < 32; kk++) {
            float a[4];
#pragma unroll
            for (int i = 0; i < 4; i++) a[i] = Wp[ty * 4 + i][kk];
            const float4* F4 = (const float4*)&Fs[kk][0];
            float4 b0 = F4[tx * 2 + 0];
            float4 b1 = F4[tx * 2 + 1];
            float bb[8] = {b0.x, b0.y, b0.z, b0.w, b1.x, b1.y, b1.z, b1.w};
#pragma unroll
            for (int i = 0; i < 4; i++)
#pragma unroll
                for (int j = 0; j < 8; j++) acc[i][j] += a[i] * bb[j];
        }
        __syncthreads();
    }
#pragma unroll
    for (int i = 0; i < 4; i++)
#pragma unroll
        for (int j = 0; j < 8; j++)
            g_Wpart[(split * DD + d0 + ty * 4 + i) * 128 + tx * 8 + j] = acc[i][j];
}

// ---------------------------------------------------------------------------
// Kernel A2: reduce split-K partials + copy W_v into fused weight matrix
// ---------------------------------------------------------------------------
__global__ void wqkv_finalize(const float* __restrict__ W_v)
{
    int idx = blockIdx.x * blockDim.x + threadIdx.x;
    if (idx >= DD * NQ) return;
    int d = idx / NQ, j = idx % NQ;
    if (j < 128) {
        float s = 0.f;
#pragma unroll
        for (int p = 0; p < 8; p++) s += g_Wpart[(p * DD + d) * 128 + j];
        g_Wqkv[idx] = s;
    } else {
        g_Wqkv[idx] = W_v[d * KK + (j - 128)];
    }
}

// ---------------------------------------------------------------------------
// Kernel A3: biases — PARALLEL: one block per output column, tree reduce
// ---------------------------------------------------------------------------
__global__ __launch_bounds__(256) void bias_kernel(
    const float* __restrict__ b_pre,
    const float* __restrict__ Q_filt,
    const float* __restrict__ K_filt,
    const float* __restrict__ b_v)
{
    int j = blockIdx.x;                 // 0..191
    int tid = threadIdx.x;
    if (j >= 128) {
        if (tid == 0) g_bqkv[j] = b_v[j - 128];
        return;
    }
    const float* F = (j < 64) ? Q_filt : K_filt;
    int col = j & 63;
    float s = 0.f;
    for (int t = tid; t < TT; t += 256)
        s += b_pre[t] * F[t * KK + col];
    // warp reduce
#pragma unroll
    for (int o = 16; o > 0; o >>= 1)
        s += __shfl_xor_sync(0xffffffff, s, o);
    __shared__ float red[8];
    if ((tid & 31) == 0) red[tid >> 5] = s;
    __syncthreads();
    if (tid == 0) {
        float tot = 0.f;
#pragma unroll
        for (int w = 0; w < 8; w++) tot += red[w];
        g_bqkv[j] = tot;
    }
}

// ---------------------------------------------------------------------------
// Split kernels: fp32 -> bf16 hi/lo pairs
// ---------------------------------------------------------------------------
__global__ __launch_bounds__(256) void split_x(const float* __restrict__ x)
{
    int i = blockIdx.x * blockDim.x + threadIdx.x;   // one float4 per thread
    float4 v = ((const float4*)x)[i];
    __nv_bfloat16 h[4], l[4];
    float f[4] = {v.x, v.y, v.z, v.w};
#pragma unroll
    for (int j = 0; j < 4; j++) {
        h[j] = __float2bfloat16_rn(f[j]);
        l[j] = __float2bfloat16_rn(f[j] - __bfloat162float(h[j]));
    }
    *(uint2*)&g_xhi[i * 4] = *(uint2*)h;
    *(uint2*)&g_xlo[i * 4] = *(uint2*)l;
}

__global__ __launch_bounds__(256) void split_w()
{
    int i = blockIdx.x * blockDim.x + threadIdx.x;   // one float4 per thread
    float4 v = ((const float4*)g_Wqkv)[i];
    __nv_bfloat16 h[4], l[4];
    float f[4] = {v.x, v.y, v.z, v.w};
#pragma unroll
    for (int j = 0; j < 4; j++) {
        h[j] = __float2bfloat16_rn(f[j]);
        l[j] = __float2bfloat16_rn(f[j] - __bfloat162float(h[j]));
    }
    *(uint2*)&g_Whi[i * 4] = *(uint2*)h;
    *(uint2*)&g_Wlo[i * 4] = *(uint2*)l;
}

// ---------------------------------------------------------------------------
// Kernel B: QKV GEMM on tensor cores, bf16 split (3 phases packed as K=3072)
// phase 0: A_hi*B_hi ; phase 1: A_lo*B_hi ; phase 2: A_hi*B_lo
// Block tile 128x64, 8 warps (4m x 2n), warp tile 32x32, k-step 32.
// ---------------------------------------------------------------------------
#define APITCH 40
#define BPITCH 72
__global__ __launch_bounds__(256) void qkv_mma()
{
    __shared__ __nv_bfloat16 As[128][APITCH];
    __shared__ __nv_bfloat16 Bs[32][BPITCH];
    int r0 = blockIdx.x * 128;
    int n0 = blockIdx.y * 64;
    int tid = threadIdx.x;
    int lane = tid & 31, w = tid >> 5;
    int wm = (w & 3) * 32, wn = (w >> 2) * 32;

    float acc[2][4][4];
#pragma unroll
    for (int mt = 0; mt < 2; mt++)
#pragma unroll
        for (int nt = 0; nt < 4; nt++)
#pragma unroll
            for (int r = 0; r < 4; r++) acc[mt][nt][r] = 0.f;

    // per-thread global load coords
    int ar = tid >> 2, ac = (tid & 3) * 8;      // A: rows ar, ar+64 ; 8 bf16 each
    int br = tid >> 3, bc = (tid & 7) * 8;      // B: one 8-bf16 vector

    float4 a0v, a1v, bv;
    // prefetch tile 0
    {
        const __nv_bfloat16* Asrc = g_xhi;
        const __nv_bfloat16* Bsrc = g_Whi;
        a0v = *(const float4*)&Asrc[(r0 + ar) * DD + ac];
        a1v = *(const float4*)&Asrc[(r0 + ar + 64) * DD + ac];
        bv  = *(const float4*)&Bsrc[br * NQ + n0 + bc];
    }

    for (int it = 0; it < 96; it++) {
        // commit prefetched tile to smem
        *(float4*)&As[ar][ac]      = a0v;
        *(float4*)&As[ar + 64][ac] = a1v;
        *(float4*)&Bs[br][bc]      = bv;
        __syncthreads();

        // prefetch next tile
        if (it + 1 < 96) {
            int kt = (it + 1) * 32;
            int phase = kt >> 10;
            int kk = kt & 1023;
            const __nv_bfloat16* Asrc = (phase == 1) ? g_xlo : g_xhi;
            const __nv_bfloat16* Bsrc = (phase == 2) ? g_Wlo : g_Whi;
            a0v = *(const float4*)&Asrc[(r0 + ar) * DD + kk + ac];
            a1v = *(const float4*)&Asrc[(r0 + ar + 64) * DD + kk + ac];
            bv  = *(const float4*)&Bsrc[(kk + br) * NQ + n0 + bc];
        }

        // compute 2 k16 steps
#pragma unroll
        for (int ks = 0; ks < 2; ks++) {
            int k = ks * 16;
            uint32_t a[2][4];
#pragma unroll
            for (int mt = 0; mt < 2; mt++) {
                uint32_t ad = smaddr(&As[wm + mt * 16 + (lane & 15)][k + ((lane >> 4) << 3)]);
                ldsm_x4(a[mt][0], a[mt][1], a[mt][2], a[mt][3], ad);
            }
            uint32_t b[2][4];
#pragma unroll
            for (int nb = 0; nb < 2; nb++) {
                uint32_t bd = smaddr(&Bs[k + (lane & 15)][wn + nb * 16 + ((lane >> 4) << 3)]);
                ldsm_x4_t(b[nb][0], b[nb][1], b[nb][2], b[nb][3], bd);
            }
#pragma unroll
            for (int mt = 0; mt < 2; mt++)
#pragma unroll
                for (int nt = 0; nt < 4; nt++) {
                    int nb = nt >> 1, pr = nt & 1;
                    mma_bf16(acc[mt][nt], a[mt], b[nb][pr * 2], b[nb][pr * 2 + 1]);
                }
        }
        __syncthreads();
    }

    // epilogue: add bias, write fp32 QKV
    int gr = lane >> 2, tc = (lane & 3) * 2;
#pragma unroll
    for (int mt = 0; mt < 2; mt++)
#pragma unroll
        for (int nt = 0; nt < 4; nt++) {
            int row = r0 + wm + mt * 16 + gr;
            int col = n0 + wn + nt * 8 + tc;
            float bb0 = g_bqkv[col], bb1 = g_bqkv[col + 1];
            g_QKV[row * NQ + col]           = acc[mt][nt][0] + bb0;
            g_QKV[row * NQ + col + 1]       = acc[mt][nt][1] + bb1;
            g_QKV[(row + 8) * NQ + col]     = acc[mt][nt][2] + bb0;
            g_QKV[(row + 8) * NQ + col + 1] = acc[mt][nt][3] + bb1;
        }
}

// ---------------------------------------------------------------------------
// Kernel C1: per-chunk state sums  S_c[p,n] = sum_s decay_s * V[s,p]*Kf[s,n]
// ---------------------------------------------------------------------------
__global__ __launch_bounds__(256) void chunk_sum(const float* __restrict__ decay)
{
    __shared__ float Vs[64][65];
    __shared__ float Ks[64][65];
    int b = blockIdx.x >> 4, c = blockIdx.x & 15;
    int base = b * TT + c * CH;
    int tid = threadIdx.x;
    int ty = tid >> 4, tx = tid & 15;
    float acc[4][4];
#pragma unroll
    for (int i = 0; i < 4; i++)
#pragma unroll
        for (int j = 0; j < 4; j++) acc[i][j] = 0.f;

    for (int st = 0; st < CH; st += 64) {
        for (int i = tid; i < 64 * 64; i += 256) {
            int r = i >> 6, k = i & 63;
            int row = base + st + r;
            float d = decay[c * CH + st + r];
            Vs[r][k] = g_QKV[row * NQ + 128 + k];
            Ks[r][k] = g_QKV[row * NQ + 64 + k] * d;
        }
        __syncthreads();
#pragma unroll 8
        for (int s = 0; s < 64; s++) {
            float a[4], bb[4];
#pragma unroll
            for (int i = 0; i < 4; i++) a[i] = Vs[s][ty * 4 + i];
#pragma unroll
            for (int j = 0; j < 4; j++) bb[j] = Ks[s][tx * 4 + j];
#pragma unroll
            for (int i = 0; i < 4; i++)
#pragma unroll
                for (int j = 0; j < 4; j++) acc[i][j] += a[i] * bb[j];
        }
        __syncthreads();
    }
    int sb = (b * NC + c) * KK * KK;
#pragma unroll
    for (int i = 0; i < 4; i++)
#pragma unroll
        for (int j = 0; j < 4; j++)
            g_S[sb + (ty * 4 + i) * KK + tx * 4 + j] = acc[i][j];
}

// ---------------------------------------------------------------------------
// Kernel C2: exclusive prefix over chunks
// ---------------------------------------------------------------------------
__global__ void chunk_prefix()
{
    int b = blockIdx.x >> 2;
    int e = (blockIdx.x & 3) * 1024 + threadIdx.x;
    float acc = 0.f;
    for (int c = 0; c < NC; c++) {
        int idx = (b * NC + c) * KK * KK + e;
        g_H[idx] = acc;
        acc += g_S[idx];
    }
}

// ---------------------------------------------------------------------------
// Kernel C3: Y_chunk = Q @ H_prev  +  causal intra-chunk (Q.V) decay Kf
// ---------------------------------------------------------------------------
__global__ __launch_bounds__(256) void attn_kernel(const float* __restrict__ decay)
{
    __shared__ float Qt[KK][CH];
    __shared__ float Reg[4096];
    int b = blockIdx.x >> 4, c = blockIdx.x & 15;
    int base = b * TT + c * CH;
    int tid = threadIdx.x;
    int row = tid >> 1;
    int half = tid & 1;

    for (int i = tid; i < KK * CH; i += 256) {
        int r = i & (CH - 1), k = i >> 7;
        Qt[k][r] = g_QKV[(base + r) * NQ + k];
    }
    int hb = (b * NC + c) * KK * KK;
    for (int i = tid; i < KK * KK; i += 256) Reg[i] = g_H[hb + i];
    __syncthreads();

    float q[KK];
#pragma unroll
    for (int k = 0; k < KK; k++) q[k] = Qt[k][row];

    float y[32];
#pragma unroll
    for (int j = 0; j < 32; j++) y[j] = 0.f;

    {
        const float4* H4 = (const float4*)Reg;
#pragma unroll
        for (int k = 0; k < KK; k++) {
            float qk = q[k];
#pragma unroll
            for (int jj = 0; jj < 8; jj++) {
                float4 h = H4[k * 16 + half * 8 + jj];
                y[jj * 4 + 0] += qk * h.x;
                y[jj * 4 + 1] += qk * h.y;
                y[jj * 4 + 2] += qk * h.z;
                y[jj * 4 + 3] += qk * h.w;
            }
        }
    }
    __syncthreads();

    for (int st = 0; st < CH; st += 32) {
        for (int i = tid; i < 2048; i += 256) {
            int s = i >> 6, k = i & 63;
            int grow = (base + st + s) * NQ;
            Reg[i]        = g_QKV[grow + 128 + k];
            Reg[2048 + i] = g_QKV[grow + 64 + k] * decay[c * CH + st + s];
        }
        __syncthreads();
        if (row >= st) {
            int sm = row - st + 1;
            if (sm > 32) sm = 32;
            const float4* V4 = (const float4*)Reg;
            const float4* F4 = (const float4*)(Reg + 2048);
            for (int s = 0; s < sm; s++) {
                float sc = 0.f;
#pragma unroll
                for (int kk = 0; kk < 16; kk++) {
                    float4 v = V4[s * 16 + kk];
                    sc += q[kk * 4 + 0] * v.x + q[kk * 4 + 1] * v.y
                        + q[kk * 4 + 2] * v.z + q[kk * 4 + 3] * v.w;
                }
#pragma unroll
                for (int jj = 0; jj < 8; jj++) {
                    float4 f = F4[s * 16 + half * 8 + jj];
                    y[jj * 4 + 0] += sc * f.x;
                    y[jj * 4 + 1] += sc * f.y;
                    y[jj * 4 + 2] += sc * f.z;
                    y[jj * 4 + 3] += sc * f.w;
                }
            }
        }
        __syncthreads();
    }

    float* yout = &g_Y[(base + row) * KK + half * 32];
#pragma unroll
    for (int jj = 0; jj < 8; jj++) {
        float4 o = {y[jj * 4 + 0], y[jj * 4 + 1], y[jj * 4 + 2], y[jj * 4 + 3]};
        *(float4*)&yout[jj * 4] = o;
    }
}

// ---------------------------------------------------------------------------
// Kernel D: out = Y[8192,64] @ W_o[64,1024] + b_o
// ---------------------------------------------------------------------------
__global__ __launch_bounds__(256) void out_gemm(const float* __restrict__ W_o,
                                                const float* __restrict__ b_o,
                                                float* __restrict__ out)
{
    __shared__ float Yt[32][65];
    __shared__ float Wos[32][128];
    int r0 = blockIdx.x * 64;
    int n0 = blockIdx.y * 128;
    int tid = threadIdx.x;
    int ty = tid >> 4, tx = tid & 15;
    float acc[4][8];
#pragma unroll
    for (int i = 0; i < 4; i++)
#pragma unroll
        for (int j = 0; j < 8; j++) acc[i][j] = 0.f;

    for (int kt = 0; kt < KK; kt += 32) {
        for (int i = tid; i < 64 * 32; i += 256) {
            int r = i >> 5, c = i & 31;
            Yt[c][r] = g_Y[(r0 + r) * KK + kt + c];
        }
        for (int i = tid; i < 32 * 128; i += 256) {
            int r = i >> 7, c = i & 127;
            Wos[r][c] = W_o[(kt + r) * DD + n0 + c];
        }
        __syncthreads();
#pragma unroll
        for (int kk = 0; kk < 32; kk++) {
            float a[4];
#pragma unroll
            for (int i = 0; i < 4; i++) a[i] = Yt[kk][ty * 4 + i];
            const float4* W4 = (const float4*)&Wos[kk][0];
            float4 b0 = W4[tx * 2 + 0];
            float4 b1 = W4[tx * 2 + 1];
            float bb[8] = {b0.x, b0.y, b0.z, b0.w, b1.x, b1.y, b1.z, b1.w};
#pragma unroll
            for (int i = 0; i < 4; i++)
#pragma unroll
                for (int j = 0; j < 8; j++) acc[i][j] += a[i] * bb[j];
        }
        __syncthreads();
    }
    float4 bl = *(const float4*)&b_o[n0 + tx * 8];
    float4 bh = *(const float4*)&b_o[n0 + tx * 8 + 4];
    float bias[8] = {bl.x, bl.y, bl.z, bl.w, bh.x, bh.y, bh.z, bh.w};
#pragma unroll
    for (int i = 0; i < 4; i++) {
        int row = r0 + ty * 4 + i;
        float4 o0 = {acc[i][0] + bias[0], acc[i][1] + bias[1],
                     acc[i][2] + bias[2], acc[i][3] + bias[3]};
        float4 o1 = {acc[i][4] + bias[4], acc[i][5] + bias[5],
                     acc[i][6] + bias[6], acc[i][7] + bias[7]};
        *(float4*)&out[row * DD + n0 + tx * 8]     = o0;
        *(float4*)&out[row * DD + n0 + tx * 8 + 4] = o1;
    }
}

// ---------------------------------------------------------------------------
extern "C" void kernel_launch(void* const* d_in, const int* in_sizes, int n_in,
                              void* d_out, int out_size)
{
    const float* x      = (const float*)d_in[0];
    const float* W_pre  = (const float*)d_in[1];
    const float* b_pre  = (const float*)d_in[2];
    const float* Q_filt = (const float*)d_in[3];
    const float* K_filt = (const float*)d_in[4];
    const float* W_v    = (const float*)d_in[5];
    const float* b_v    = (const float*)d_in[6];
    const float* W_o    = (const float*)d_in[7];
    const float* b_o    = (const float*)d_in[8];
    const float* decay  = (const float*)d_in[9];
    float* out = (float*)d_out;

    split_x<<<(RR * DD / 4) / 256, 256>>>(x);
    wfilt_partial<<<dim3(16, 8), 256>>>(W_pre, Q_filt, K_filt);
    wqkv_finalize<<<(DD * NQ + 255) / 256, 256>>>(W_v);
    bias_kernel<<<192, 256>>>(b_pre, Q_filt, K_filt, b_v);
    split_w<<<(DD * NQ / 4) / 256, 256>>>();
    qkv_mma<<<dim3(64, 3), 256>>>();
    chunk_sum<<<64, 256>>>(decay);
    chunk_prefix<<<16, 1024>>>();
    attn_kernel<<<64, 256>>>(decay);
    out_gemm<<<dim3(128, 8), 256>>>(W_o, b_o, out);
}